// round 2
// baseline (speedup 1.0000x reference)
#include <cuda_runtime.h>
#include <cuda_bf16.h>

#define MAX_STEPS 20
#define THRESHOLD 0.99f

// ---------------------------------------------------------------------------
// Scalar ACT recursion (mirrors the reference scan exactly, per row).
// p = sigmoid(x.W + b) is constant across the 20 steps, so the state
// recursion collapses to state = m * x with m from this scalar loop.
// ---------------------------------------------------------------------------
__device__ __forceinline__ void act_scalar(float p, float& m, float& ponder) {
    float hp = 0.0f, rem = 0.0f, nup = 0.0f;
    m = 0.0f;
#pragma unroll
    for (int s = 0; s < MAX_STEPS; s++) {
        float still = (hp < 1.0f) ? 1.0f : 0.0f;
        float hpn = hp + p * still;
        float nh = (hpn > THRESHOLD) ? still : 0.0f;   // new_halted
        hp = hpn;
        rem = rem + nh * (1.0f - hp);
        hp = hp + nh * rem;                             // exact 1.0 on halt
        float w = p * still + nh * rem;                 // update_weights
        m = (1.0f - w) * m + w;
        nup += still;
    }
    ponder = nup + rem;
}

__device__ __forceinline__ void stcs_f4(float4* p, float4 v) {
    // streaming store: state is write-once, evict-first in L2
    asm volatile("st.global.cs.v4.f32 [%0], {%1,%2,%3,%4};"
                 :: "l"(p), "f"(v.x), "f"(v.y), "f"(v.z), "f"(v.w)
                 : "memory");
}

// ---------------------------------------------------------------------------
// D == 1024 specialization: one warp per row. Each lane holds 8 float4 of
// the row in registers (x read exactly once, reused for the writeback).
// W staged in shared memory.
// ---------------------------------------------------------------------------
__global__ __launch_bounds__(256, 4)
void act_kernel_d1024(const float* __restrict__ x,
                      const float* __restrict__ W,
                      const float* __restrict__ b,
                      float* __restrict__ state,
                      float* __restrict__ ponder,
                      int rows, int write_ponder)
{
    __shared__ float4 sW[256];   // 1024 floats of W
    const int tid = threadIdx.x;
    sW[tid] = reinterpret_cast<const float4*>(W)[tid];
    __syncthreads();

    const int warp = tid >> 5;
    const int lane = tid & 31;
    const long long row = (long long)blockIdx.x * 8 + warp;
    if (row >= rows) return;

    const float4* xr = reinterpret_cast<const float4*>(x) + row * 256;

    float4 v[8];
    float dot = 0.0f;
#pragma unroll
    for (int c = 0; c < 8; c++) {
        const int i = lane + 32 * c;
        v[c] = __ldg(&xr[i]);
        const float4 w = sW[i];
        dot = fmaf(v[c].x, w.x, dot);
        dot = fmaf(v[c].y, w.y, dot);
        dot = fmaf(v[c].z, w.z, dot);
        dot = fmaf(v[c].w, w.w, dot);
    }
#pragma unroll
    for (int o = 16; o; o >>= 1)
        dot += __shfl_xor_sync(0xffffffffu, dot, o);

    const float z = dot + b[0];
    const float p = 1.0f / (1.0f + expf(-z));

    float m, pt;
    act_scalar(p, m, pt);

    float4* sr = reinterpret_cast<float4*>(state) + row * 256;
#pragma unroll
    for (int c = 0; c < 8; c++) {
        const int i = lane + 32 * c;
        float4 o;
        o.x = m * v[c].x; o.y = m * v[c].y;
        o.z = m * v[c].z; o.w = m * v[c].w;
        stcs_f4(&sr[i], o);
    }
    if (lane == 0 && write_ponder) ponder[row] = pt;
}

// ---------------------------------------------------------------------------
// Generic fallback (any D): one block per row, two-pass over x.
// ---------------------------------------------------------------------------
__global__ __launch_bounds__(256)
void act_kernel_generic(const float* __restrict__ x,
                        const float* __restrict__ W,
                        const float* __restrict__ b,
                        float* __restrict__ state,
                        float* __restrict__ ponder,
                        int rows, int D, int write_ponder)
{
    __shared__ float red[8];
    __shared__ float s_m;
    const int row = blockIdx.x;
    if (row >= rows) return;
    const int tid = threadIdx.x;
    const float* xr = x + (long long)row * D;

    float dot = 0.0f;
    for (int i = tid; i < D; i += blockDim.x)
        dot = fmaf(xr[i], W[i], dot);
#pragma unroll
    for (int o = 16; o; o >>= 1)
        dot += __shfl_xor_sync(0xffffffffu, dot, o);
    if ((tid & 31) == 0) red[tid >> 5] = dot;
    __syncthreads();
    if (tid == 0) {
        float d = 0.0f;
        for (int wi = 0; wi < (int)(blockDim.x >> 5); wi++) d += red[wi];
        const float z = d + b[0];
        const float p = 1.0f / (1.0f + expf(-z));
        float m, pt;
        act_scalar(p, m, pt);
        s_m = m;
        if (write_ponder) ponder[row] = pt;
    }
    __syncthreads();
    const float m = s_m;
    float* sr = state + (long long)row * D;
    for (int i = tid; i < D; i += blockDim.x)
        sr[i] = m * xr[i];
}

extern "C" void kernel_launch(void* const* d_in, const int* in_sizes, int n_in,
                              void* d_out, int out_size)
{
    const float* x = (const float*)d_in[0];
    const float* W = (const float*)d_in[1];
    const float* b = (const float*)d_in[2];

    const int D = in_sizes[1];                 // W is (D, 1)
    const int rows = in_sizes[0] / D;          // B*S

    float* out = (float*)d_out;
    float* state = out;
    float* ponder = out + (long long)rows * D;
    const int write_ponder =
        ((long long)out_size >= (long long)rows * D + rows) ? 1 : 0;

    if (D == 1024) {
        const int blocks = (rows + 7) / 8;     // 8 warps (rows) per block
        act_kernel_d1024<<<blocks, 256>>>(x, W, b, state, ponder, rows,
                                          write_ponder);
    } else {
        act_kernel_generic<<<rows, 256>>>(x, W, b, state, ponder, rows, D,
                                          write_ponder);
    }
}